// round 1
// baseline (speedup 1.0000x reference)
#include <cuda_runtime.h>

// Problem constants (fixed by the dataset)
#define MD      256        // feature dim
#define NN      30000      // nodes
#define EE      480000     // edges
#define THRESH  1e-6f
// iterations: ref does up to 30 steps (first step from Z=0 gives Z=X), then 1 final step.

// ---------------- scratch (device globals; no allocation allowed) ----------------
__device__ float g_Zt[NN * MD];        // Z transposed: (N, M), row-contiguous in M
__device__ float g_P [NN * MD];        // P = Z*A, transposed layout (N, M)
__device__ float g_FF[MD * MD];
__device__ float g_Gg[MD * MD];        // gamma_c * F^T F / (||F^T F||_F + eps)  (symmetric)
__device__ int   g_hist[NN];
__device__ int   g_colptr[NN + 1];
__device__ int   g_colfill[NN];
__device__ int   g_srow[EE];
__device__ float g_sval[EE];
__device__ float g_norm2;
__device__ float g_diff2;
__device__ int   g_conv;

// ---------------- setup kernels ----------------
__global__ void init_kernel() {
    int i = blockIdx.x * blockDim.x + threadIdx.x;
    if (i < NN) g_hist[i] = 0;
    if (i == 0) { g_norm2 = 0.f; g_diff2 = 0.f; g_conv = 0; }
}

__global__ void hist_kernel(const int* __restrict__ cols) {
    int e = blockIdx.x * blockDim.x + threadIdx.x;
    if (e < EE) atomicAdd(&g_hist[cols[e]], 1);
}

__global__ void scan_kernel() {
    __shared__ int ssum[256];
    int t = threadIdx.x;
    const int CH = (NN + 255) / 256;           // 118
    int start = t * CH;
    int s = 0;
    for (int i = 0; i < CH; i++) {
        int idx = start + i;
        if (idx < NN) s += g_hist[idx];
    }
    ssum[t] = s;
    __syncthreads();
    // inclusive Hillis-Steele scan over 256 partials
    for (int off = 1; off < 256; off <<= 1) {
        int v = (t >= off) ? ssum[t - off] : 0;
        __syncthreads();
        ssum[t] += v;
        __syncthreads();
    }
    int pre = (t == 0) ? 0 : ssum[t - 1];
    for (int i = 0; i < CH; i++) {
        int idx = start + i;
        if (idx < NN) {
            g_colptr[idx]  = pre;
            g_colfill[idx] = pre;
            pre += g_hist[idx];
        }
    }
    if (t == 255) g_colptr[NN] = ssum[255];
}

__global__ void scatter_kernel(const int* __restrict__ rows,
                               const int* __restrict__ cols,
                               const float* __restrict__ vals) {
    int e = blockIdx.x * blockDim.x + threadIdx.x;
    if (e >= EE) return;
    int c = cols[e];
    int pos = atomicAdd(&g_colfill[c], 1);
    g_srow[pos] = rows[e];
    g_sval[pos] = vals[e];
}

// FF = F^T F, plus partial Frobenius-norm^2 accumulation
__global__ void ff_kernel(const float* __restrict__ F) {
    __shared__ float col_i[MD];
    __shared__ float red[256];
    int i = blockIdx.x;
    int t = threadIdx.x;
    col_i[t] = F[t * MD + i];                  // column i of F
    __syncthreads();
    float acc = 0.f;
    #pragma unroll 8
    for (int k = 0; k < MD; k++)
        acc += col_i[k] * F[k * MD + t];
    g_FF[i * MD + t] = acc;
    red[t] = acc * acc;
    __syncthreads();
    for (int s = 128; s > 0; s >>= 1) {
        if (t < s) red[t] += red[t + s];
        __syncthreads();
    }
    if (t == 0) atomicAdd(&g_norm2, red[0]);
}

__global__ void scale_kernel(const float* __restrict__ gamma) {
    int idx = blockIdx.x * blockDim.x + threadIdx.x;
    float gc = fminf(fmaxf(gamma[0], 0.f), 1.f);
    float scale = gc / (sqrtf(g_norm2) + 1e-12f);
    g_Gg[idx] = g_FF[idx] * scale;
}

// Z1 = X (first iteration from Z0=0), stored transposed
__global__ void transpose_x_kernel(const float* __restrict__ X) {
    __shared__ float tile[32][33];
    int nb = blockIdx.x * 32, mb = blockIdx.y * 32;
    int tx = threadIdx.x, ty = threadIdx.y;    // 32 x 8
    #pragma unroll
    for (int i = ty; i < 32; i += 8) {
        int m = mb + i, n = nb + tx;
        tile[i][tx] = (n < NN) ? X[m * NN + n] : 0.f;
    }
    __syncthreads();
    #pragma unroll
    for (int i = ty; i < 32; i += 8) {
        int n = nb + i, m = mb + tx;
        if (n < NN) g_Zt[n * MD + m] = tile[tx][i];
    }
}

// ---------------- iteration kernels ----------------
// P[c, :] = sum_{e in column c} val_e * Zt[row_e, :]
__global__ void spmm_kernel(int guard) {
    if (guard && g_conv) return;
    int c = blockIdx.x;
    int t = threadIdx.x;
    int s = g_colptr[c], e = g_colptr[c + 1];
    float acc = 0.f;
    for (int i = s; i < e; i++) {
        float v = g_sval[i];
        int   r = g_srow[i];
        acc += v * g_Zt[r * MD + t];
    }
    g_P[c * MD + t] = acc;
}

// out_t[n, m] = sum_j Gg[j, m] * P[n, j] + X[m, n]   (Gg symmetric)
// mode 0: store to g_Zt (N,M) in place, accumulate ||new-old||^2 into g_diff2
// mode 1: store to out in (M, N) layout (d_out), no diff
#define BN 64
#define BM 128
#define BK 16
__global__ void __launch_bounds__(256) gemm_kernel(const float* __restrict__ X,
                                                   float* __restrict__ out,
                                                   int mode, int guard) {
    if (guard && g_conv) return;
    __shared__ float sA[BK][BN + 4];   // +4 pad keeps float4 alignment (272B rows)
    __shared__ float sB[BK][BM + 4];   // 528B rows
    __shared__ float red[256];

    int tid = threadIdx.x;
    int tx = tid & 15;                 // n-direction (4 consecutive n each)
    int ty = tid >> 4;                 // m-direction (8 consecutive m each)
    int n0 = blockIdx.x * BN;
    int m0 = blockIdx.y * BM;

    float c[4][8];
    #pragma unroll
    for (int a = 0; a < 4; a++)
        #pragma unroll
        for (int b = 0; b < 8; b++) c[a][b] = 0.f;

    int la_n = tid >> 2;               // 0..63
    int la_k = (tid & 3) * 4;          // 0,4,8,12
    int lb_k = tid >> 4;               // 0..15
    int lb_m = (tid & 15) * 8;         // 0..120

    for (int kt = 0; kt < MD; kt += BK) {
        float4 av = make_float4(0.f, 0.f, 0.f, 0.f);
        int na = n0 + la_n;
        if (na < NN) av = *(const float4*)&g_P[na * MD + kt + la_k];
        sA[la_k + 0][la_n] = av.x;
        sA[la_k + 1][la_n] = av.y;
        sA[la_k + 2][la_n] = av.z;
        sA[la_k + 3][la_n] = av.w;
        *(float4*)&sB[lb_k][lb_m]     = *(const float4*)&g_Gg[(kt + lb_k) * MD + m0 + lb_m];
        *(float4*)&sB[lb_k][lb_m + 4] = *(const float4*)&g_Gg[(kt + lb_k) * MD + m0 + lb_m + 4];
        __syncthreads();

        #pragma unroll
        for (int k = 0; k < BK; k++) {
            float4 ra  = *(const float4*)&sA[k][tx * 4];
            float4 rb0 = *(const float4*)&sB[k][ty * 8];
            float4 rb1 = *(const float4*)&sB[k][ty * 8 + 4];
            float a[4] = {ra.x, ra.y, ra.z, ra.w};
            float b[8] = {rb0.x, rb0.y, rb0.z, rb0.w, rb1.x, rb1.y, rb1.z, rb1.w};
            #pragma unroll
            for (int nn = 0; nn < 4; nn++)
                #pragma unroll
                for (int mm = 0; mm < 8; mm++)
                    c[nn][mm] += a[nn] * b[mm];
        }
        __syncthreads();
    }

    int nbase = n0 + tx * 4;           // multiple of 4; N divisible by 4 -> whole float4 valid or not
    float v[4][8];
    #pragma unroll
    for (int mm = 0; mm < 8; mm++) {
        int m = m0 + ty * 8 + mm;
        if (nbase < NN) {
            float4 xv = *(const float4*)&X[m * NN + nbase];
            v[0][mm] = c[0][mm] + xv.x;
            v[1][mm] = c[1][mm] + xv.y;
            v[2][mm] = c[2][mm] + xv.z;
            v[3][mm] = c[3][mm] + xv.w;
        }
    }

    if (mode == 0) {
        float lsum = 0.f;
        #pragma unroll
        for (int nn = 0; nn < 4; nn++) {
            int n = nbase + nn;
            if (n < NN) {
                float* zp = &g_Zt[n * MD + m0 + ty * 8];
                float4 o0 = *(const float4*)&zp[0];
                float4 o1 = *(const float4*)&zp[4];
                float d;
                d = v[nn][0] - o0.x; lsum += d * d;
                d = v[nn][1] - o0.y; lsum += d * d;
                d = v[nn][2] - o0.z; lsum += d * d;
                d = v[nn][3] - o0.w; lsum += d * d;
                d = v[nn][4] - o1.x; lsum += d * d;
                d = v[nn][5] - o1.y; lsum += d * d;
                d = v[nn][6] - o1.z; lsum += d * d;
                d = v[nn][7] - o1.w; lsum += d * d;
                *(float4*)&zp[0] = make_float4(v[nn][0], v[nn][1], v[nn][2], v[nn][3]);
                *(float4*)&zp[4] = make_float4(v[nn][4], v[nn][5], v[nn][6], v[nn][7]);
            }
        }
        red[tid] = lsum;
        __syncthreads();
        for (int s = 128; s > 0; s >>= 1) {
            if (tid < s) red[tid] += red[tid + s];
            __syncthreads();
        }
        if (tid == 0) atomicAdd(&g_diff2, red[0]);
    } else {
        if (nbase < NN) {
            #pragma unroll
            for (int mm = 0; mm < 8; mm++) {
                int m = m0 + ty * 8 + mm;
                *(float4*)&out[m * NN + nbase] =
                    make_float4(v[0][mm], v[1][mm], v[2][mm], v[3][mm]);
            }
        }
    }
}

__global__ void check_kernel() {
    if (!g_conv) {
        if (sqrtf(g_diff2) <= THRESH) g_conv = 1;
    }
    g_diff2 = 0.f;
}

// ---------------- launch ----------------
extern "C" void kernel_launch(void* const* d_in, const int* in_sizes, int n_in,
                              void* d_out, int out_size) {
    const float* F     = (const float*)d_in[0];
    const float* gamma = (const float*)d_in[1];
    const float* X     = (const float*)d_in[2];
    const float* vals  = (const float*)d_in[3];
    const int*   rows  = (const int*)d_in[4];
    const int*   cols  = (const int*)d_in[5];
    float* out = (float*)d_out;

    // Build CSC of A (by column) + Gg
    init_kernel<<<(NN + 255) / 256, 256>>>();
    hist_kernel<<<(EE + 255) / 256, 256>>>(cols);
    scan_kernel<<<1, 256>>>();
    scatter_kernel<<<(EE + 255) / 256, 256>>>(rows, cols, vals);
    ff_kernel<<<MD, 256>>>(F);
    scale_kernel<<<MD, 256>>>(gamma);

    // iteration 1: Z = X  (step from Z0 = 0; diff = ||X|| > thresh always)
    dim3 tg((NN + 31) / 32, MD / 32);
    transpose_x_kernel<<<tg, dim3(32, 8)>>>(X);

    dim3 gg((NN + BN - 1) / BN, MD / BM);
    // iterations 2..30, with device-side convergence gating (matches reference loop)
    for (int it = 2; it <= 30; it++) {
        spmm_kernel<<<NN, MD>>>(1);
        gemm_kernel<<<gg, 256>>>(X, nullptr, 0, 1);
        check_kernel<<<1, 1>>>();
    }
    // final extra step at the (approx) fixed point -> d_out in (M, N) layout
    spmm_kernel<<<NN, MD>>>(0);
    gemm_kernel<<<gg, 256>>>(X, out, 1, 0);
}